// round 15
// baseline (speedup 1.0000x reference)
#include <cuda_runtime.h>
#include <cstdint>
#include <cstddef>

// ---------------------------------------------------------------------------
// ScalEdgesRead: out[b,e,:] = (hs[b,src[e],:] + hd[b,dst[e],:]) * 1/sqrt(2)
//   hs = x @ W_src^T, hd = x @ W_dst^T     (B=2, N=50000, E=800000, D=64)
// Phase 1: node transform (FFMA2), split into 4 launches (ncu visibility).
// Phase 2: edge gather — branchless int32 indexing, front-batched LDG.128.
// NOTE: src/dst arrive as int32 (JAX x64 disabled demotes jnp.int64).
// ---------------------------------------------------------------------------

#define INV_SQRT_2 0.70710678118654752440f

#define FMA_F32X2(d, a, b, c) \
    asm("fma.rn.f32x2 %0, %1, %2, %3;" : "=l"(d) : "l"(a), "l"(b), "l"(c))

// Scratch: hs/hd, 64 floats per (b,n) row. M = B*N = 100000 rows here.
static constexpr int MAX_M = 100352;  // >= 100000, multiple of 64
__device__ float g_hs[(size_t)MAX_M * 64];
__device__ float g_hd[(size_t)MAX_M * 64];

// ---------------------------------------------------------------------------
// Phase 1: 64-row x 128-col tile per block, 128 threads, 8 rows x 8 cols each.
// Dynamic smem (64 KB): Xd [64 rows][64 k] float2 DUPLICATED ({x,x}) so the
// broadcast A-operand of fma.rn.f32x2 comes straight from one LDS.64;
// Ws [64 k][128 j] so adjacent column pairs come packed from LDS.128.
// ---------------------------------------------------------------------------
__global__ __launch_bounds__(128) void transform_kernel(
    const float* __restrict__ x,
    const float* __restrict__ Wsrc,   // (64, 64) row-major: W[j*64 + k]
    const float* __restrict__ Wdst,
    int row_start, int M)
{
    extern __shared__ char smem[];
    float2* Xd = reinterpret_cast<float2*>(smem);                 // [64][64], 32 KB
    float*  Ws = reinterpret_cast<float*>(smem + 32 * 1024);      // [64][128], 32 KB

    const int tid  = threadIdx.x;
    const int row0 = row_start + blockIdx.x * 64;

    // Load W transposed into shared: Ws[k*128 + j].
    for (int idx = tid; idx < 128 * 64; idx += 128) {
        int j = idx >> 6;
        int k = idx & 63;
        float v = (j < 64) ? Wsrc[j * 64 + k] : Wdst[(j - 64) * 64 + k];
        Ws[k * 128 + j] = v;
    }
    // Load X tile (float4, coalesced) and store duplicated {x,x}.
    for (int idx = tid; idx < 64 * 16; idx += 128) {
        int r  = idx >> 4;
        int c4 = idx & 15;
        int gr = row0 + r;
        float4 v = make_float4(0.f, 0.f, 0.f, 0.f);
        if (gr < M) v = reinterpret_cast<const float4*>(x)[(size_t)gr * 16 + c4];
        float2* p = &Xd[r * 64 + c4 * 4];
        p[0] = make_float2(v.x, v.x);
        p[1] = make_float2(v.y, v.y);
        p[2] = make_float2(v.z, v.z);
        p[3] = make_float2(v.w, v.w);
    }
    __syncthreads();

    const int tx = tid & 15;          // column group: 16 groups of 8 cols
    const int ty = tid >> 4;          // row group:     8 groups of 8 rows
    const int rb = ty * 8;
    const int cb = tx * 8;

    unsigned long long acc2[8][4];    // [row][col-pair], f32x2 accumulators
#pragma unroll
    for (int i = 0; i < 8; ++i)
#pragma unroll
        for (int p = 0; p < 4; ++p) acc2[i][p] = 0ull;

#pragma unroll 4
    for (int k = 0; k < 64; ++k) {
        unsigned long long aa[8];
#pragma unroll
        for (int i = 0; i < 8; ++i)
            aa[i] = *reinterpret_cast<const unsigned long long*>(&Xd[(rb + i) * 64 + k]);

        ulonglong2 bq0 = *reinterpret_cast<const ulonglong2*>(&Ws[k * 128 + cb]);
        ulonglong2 bq1 = *reinterpret_cast<const ulonglong2*>(&Ws[k * 128 + cb + 4]);

#pragma unroll
        for (int i = 0; i < 8; ++i) {
            FMA_F32X2(acc2[i][0], aa[i], bq0.x, acc2[i][0]);
            FMA_F32X2(acc2[i][1], aa[i], bq0.y, acc2[i][1]);
            FMA_F32X2(acc2[i][2], aa[i], bq1.x, acc2[i][2]);
            FMA_F32X2(acc2[i][3], aa[i], bq1.y, acc2[i][3]);
        }
    }

    // Write: tx<8 -> hs cols [cb, cb+8), tx>=8 -> hd cols [cb-64, cb-56)
    float* outbuf = (tx < 8) ? g_hs : g_hd;
    const int ccol = (tx < 8) ? cb : (cb - 64);
#pragma unroll
    for (int i = 0; i < 8; ++i) {
        int gr = row0 + rb + i;
        if (gr < M) {
            float4 o0, o1;
            o0.x = __uint_as_float((unsigned)(acc2[i][0] & 0xffffffffull));
            o0.y = __uint_as_float((unsigned)(acc2[i][0] >> 32));
            o0.z = __uint_as_float((unsigned)(acc2[i][1] & 0xffffffffull));
            o0.w = __uint_as_float((unsigned)(acc2[i][1] >> 32));
            o1.x = __uint_as_float((unsigned)(acc2[i][2] & 0xffffffffull));
            o1.y = __uint_as_float((unsigned)(acc2[i][2] >> 32));
            o1.z = __uint_as_float((unsigned)(acc2[i][3] & 0xffffffffull));
            o1.w = __uint_as_float((unsigned)(acc2[i][3] >> 32));
            float* p = outbuf + (size_t)gr * 64 + ccol;
            *reinterpret_cast<float4*>(p)     = o0;
            *reinterpret_cast<float4*>(p + 4) = o1;
        }
    }
}

// ---------------------------------------------------------------------------
// Phase 2: 256 threads/block, 4 rows per thread (64 rows/block).
// All-int32 indexing, branchless batch split (SELs, no loops/branches), then
// 8 back-to-back LDG.128 gathers (front-batched -> deep MLP). Loads are
// clamped (always in-bounds); only stores are guarded for the tail.
// ---------------------------------------------------------------------------
__global__ __launch_bounds__(256) void gather_kernel(
    const int* __restrict__ src,
    const int* __restrict__ dst,
    float* __restrict__ out,
    int E, int N, int total_rows)
{
    const int t = threadIdx.x;
    const int i = t >> 4;             // row slot within block tile (0..15)
    const int c = t & 15;             // float4 chunk within row (D=64 -> 16 f4)
    const int base = blockIdx.x * 64 + i;

    const float4* __restrict__ hs4 = reinterpret_cast<const float4*>(g_hs);
    const float4* __restrict__ hd4 = reinterpret_cast<const float4*>(g_hd);

    // ---- index phase: all address math, no data-dependent branches ----
    int rowv[4];
    size_t aoff[4], doff[4];
#pragma unroll
    for (int r = 0; r < 4; ++r) {
        int row = base + r * 16;
        rowv[r] = row;
        int rc = row < total_rows ? row : (total_rows - 1);   // clamp, not branch
        int e = rc, b = 0;
#pragma unroll
        for (int q = 0; q < 3; ++q) {                          // B<=4, pure SELs
            int ge = (e >= E);
            e -= ge ? E : 0;
            b += ge;
        }
        int sn = __ldg(src + e);     // 16 lanes same addr -> broadcast
        int dn = __ldg(dst + e);
        aoff[r] = ((size_t)(b * N + sn) << 4) + c;
        doff[r] = ((size_t)(b * N + dn) << 4) + c;
    }

    // ---- gather phase: 8 independent LDG.128 back-to-back ----
    float4 a[4], d[4];
#pragma unroll
    for (int r = 0; r < 4; ++r) a[r] = __ldg(hs4 + aoff[r]);
#pragma unroll
    for (int r = 0; r < 4; ++r) d[r] = __ldg(hd4 + doff[r]);

    // ---- combine + streaming store (guarded) ----
#pragma unroll
    for (int r = 0; r < 4; ++r) {
        if (rowv[r] < total_rows) {
            float4 o;
            o.x = (a[r].x + d[r].x) * INV_SQRT_2;
            o.y = (a[r].y + d[r].y) * INV_SQRT_2;
            o.z = (a[r].z + d[r].z) * INV_SQRT_2;
            o.w = (a[r].w + d[r].w) * INV_SQRT_2;
            __stcs(reinterpret_cast<float4*>(out) + ((size_t)rowv[r] << 4) + c, o);
        }
    }
}

// ---------------------------------------------------------------------------
extern "C" void kernel_launch(void* const* d_in, const int* in_sizes, int n_in,
                              void* d_out, int out_size)
{
    const float* x    = (const float*)d_in[0];   // (B, N, 64)
    const int*   src  = (const int*)d_in[1];     // (E,) int32
    const int*   dst  = (const int*)d_in[2];     // (E,) int32
    const float* Wsrc = (const float*)d_in[3];   // (64, 64)
    const float* Wdst = (const float*)d_in[4];   // (64, 64)

    const int D = 64;
    const int E = in_sizes[1];
    const int M = in_sizes[0] / D;               // B*N
    const int total_rows = out_size / D;         // B*E (1.6M, fits int32)
    const int B = total_rows / E;
    const int N = M / B;

    const int SMEM_BYTES = 64 * 1024;   // Xd 32 KB + Ws 32 KB
    cudaFuncSetAttribute(transform_kernel,
                         cudaFuncAttributeMaxDynamicSharedMemorySize, SMEM_BYTES);

    // Phase 1: node transform, 4 launches over row ranges (independent; also
    // shifts ncu's skip-5 capture point onto a transform chunk).
    {
        int chunk = (((M + 3) / 4) + 63) / 64 * 64;   // rows per chunk, mult of 64
        for (int s = 0; s < M; s += chunk) {
            int rows = (M - s < chunk) ? (M - s) : chunk;
            int grid = (rows + 63) / 64;
            transform_kernel<<<grid, 128, SMEM_BYTES>>>(x, Wsrc, Wdst, s, M);
        }
    }
    // Phase 2: edge gather (64 rows per block)
    {
        int blocks = (total_rows + 63) / 64;
        gather_kernel<<<blocks, 256>>>(src, dst, (float*)d_out, E, N, total_rows);
    }
}

// round 16
// speedup vs baseline: 1.0389x; 1.0389x over previous
#include <cuda_runtime.h>
#include <cstdint>
#include <cstddef>

// ---------------------------------------------------------------------------
// ScalEdgesRead: out[b,e,:] = (hs[b,src[e],:] + hd[b,dst[e],:]) * 1/sqrt(2)
//   hs = x @ W_src^T, hd = x @ W_dst^T     (B=2, N=50000, E=800000, D=64)
// Phase 1: node transform, FFMA2 + explicit software-pipelined inner loop.
// Phase 2: edge gather — branchless int32 indexing, front-batched LDG.128.
// NOTE: src/dst arrive as int32 (JAX x64 disabled demotes jnp.int64).
// ---------------------------------------------------------------------------

#define INV_SQRT_2 0.70710678118654752440f

#define FMA_F32X2(d, a, b, c) \
    asm("fma.rn.f32x2 %0, %1, %2, %3;" : "=l"(d) : "l"(a), "l"(b), "l"(c))

// Scratch: hs/hd, 64 floats per (b,n) row. M = B*N = 100000 rows here.
static constexpr int MAX_M = 100352;  // >= 100000, multiple of 64
__device__ float g_hs[(size_t)MAX_M * 64];
__device__ float g_hd[(size_t)MAX_M * 64];

// ---------------------------------------------------------------------------
// Phase 1: 64-row x 128-col tile per block, 128 threads, 8 rows x 8 cols each.
// Dynamic smem (64 KB): Xd [64 rows][64 k] float2 DUPLICATED ({x,x}) so the
// broadcast A-operand of fma.rn.f32x2 is one LDS.64; Ws [64 k][128 j] so
// adjacent column pairs come packed from LDS.128.
// Inner loop is explicitly double-buffered: LDS for k+1 issue before the
// FFMA2 block of k, so the 29-cyc LDS latency hides under 64 cyc of FFMA2.
// ---------------------------------------------------------------------------
__global__ __launch_bounds__(128) void transform_kernel(
    const float* __restrict__ x,
    const float* __restrict__ Wsrc,   // (64, 64) row-major: W[j*64 + k]
    const float* __restrict__ Wdst,
    int M)
{
    extern __shared__ char smem[];
    float2* Xd = reinterpret_cast<float2*>(smem);                 // [64][64], 32 KB
    float*  Ws = reinterpret_cast<float*>(smem + 32 * 1024);      // [64][128], 32 KB

    const int tid  = threadIdx.x;
    const int row0 = blockIdx.x * 64;

    // Load W transposed into shared: Ws[k*128 + j].
    for (int idx = tid; idx < 128 * 64; idx += 128) {
        int j = idx >> 6;
        int k = idx & 63;
        float v = (j < 64) ? Wsrc[j * 64 + k] : Wdst[(j - 64) * 64 + k];
        Ws[k * 128 + j] = v;
    }
    // Load X tile (float4, coalesced) and store duplicated {x,x}.
    for (int idx = tid; idx < 64 * 16; idx += 128) {
        int r  = idx >> 4;
        int c4 = idx & 15;
        int gr = row0 + r;
        float4 v = make_float4(0.f, 0.f, 0.f, 0.f);
        if (gr < M) v = reinterpret_cast<const float4*>(x)[(size_t)gr * 16 + c4];
        float2* p = &Xd[r * 64 + c4 * 4];
        p[0] = make_float2(v.x, v.x);
        p[1] = make_float2(v.y, v.y);
        p[2] = make_float2(v.z, v.z);
        p[3] = make_float2(v.w, v.w);
    }
    __syncthreads();

    const int tx = tid & 15;          // column group: 16 groups of 8 cols
    const int ty = tid >> 4;          // row group:     8 groups of 8 rows
    const int rb = ty * 8;
    const int cb = tx * 8;

    unsigned long long acc2[8][4];    // [row][col-pair], f32x2 accumulators
#pragma unroll
    for (int i = 0; i < 8; ++i)
#pragma unroll
        for (int p = 0; p < 4; ++p) acc2[i][p] = 0ull;

    // Double buffers.
    unsigned long long A0[8], A1[8];
    ulonglong2 B00, B01, B10, B11;

#define LOADK(KK, AA, BB0, BB1)                                                  \
    do {                                                                         \
        _Pragma("unroll")                                                        \
        for (int i = 0; i < 8; ++i)                                              \
            AA[i] = *reinterpret_cast<const unsigned long long*>(                \
                &Xd[(rb + i) * 64 + (KK)]);                                      \
        BB0 = *reinterpret_cast<const ulonglong2*>(&Ws[(KK) * 128 + cb]);        \
        BB1 = *reinterpret_cast<const ulonglong2*>(&Ws[(KK) * 128 + cb + 4]);    \
    } while (0)

#define FMAK(AA, BB0, BB1)                                                       \
    do {                                                                         \
        _Pragma("unroll")                                                        \
        for (int i = 0; i < 8; ++i) {                                            \
            FMA_F32X2(acc2[i][0], AA[i], BB0.x, acc2[i][0]);                     \
            FMA_F32X2(acc2[i][1], AA[i], BB0.y, acc2[i][1]);                     \
            FMA_F32X2(acc2[i][2], AA[i], BB1.x, acc2[i][2]);                     \
            FMA_F32X2(acc2[i][3], AA[i], BB1.y, acc2[i][3]);                     \
        }                                                                        \
    } while (0)

    LOADK(0, A0, B00, B01);
#pragma unroll 2
    for (int k = 0; k < 62; k += 2) {
        LOADK(k + 1, A1, B10, B11);
        FMAK(A0, B00, B01);
        LOADK(k + 2, A0, B00, B01);
        FMAK(A1, B10, B11);
    }
    LOADK(63, A1, B10, B11);
    FMAK(A0, B00, B01);   // k = 62
    FMAK(A1, B10, B11);   // k = 63
#undef LOADK
#undef FMAK

    // Write: tx<8 -> hs cols [cb, cb+8), tx>=8 -> hd cols [cb-64, cb-56)
    float* outbuf = (tx < 8) ? g_hs : g_hd;
    const int ccol = (tx < 8) ? cb : (cb - 64);
#pragma unroll
    for (int i = 0; i < 8; ++i) {
        int gr = row0 + rb + i;
        if (gr < M) {
            float4 o0, o1;
            o0.x = __uint_as_float((unsigned)(acc2[i][0] & 0xffffffffull));
            o0.y = __uint_as_float((unsigned)(acc2[i][0] >> 32));
            o0.z = __uint_as_float((unsigned)(acc2[i][1] & 0xffffffffull));
            o0.w = __uint_as_float((unsigned)(acc2[i][1] >> 32));
            o1.x = __uint_as_float((unsigned)(acc2[i][2] & 0xffffffffull));
            o1.y = __uint_as_float((unsigned)(acc2[i][2] >> 32));
            o1.z = __uint_as_float((unsigned)(acc2[i][3] & 0xffffffffull));
            o1.w = __uint_as_float((unsigned)(acc2[i][3] >> 32));
            float* p = outbuf + (size_t)gr * 64 + ccol;
            *reinterpret_cast<float4*>(p)     = o0;
            *reinterpret_cast<float4*>(p + 4) = o1;
        }
    }
}

// ---------------------------------------------------------------------------
// Phase 2: 256 threads/block, 4 rows per thread (64 rows/block).
// All-int32 indexing, branchless batch split (SELs), then 8 back-to-back
// LDG.128 gathers (front-batched -> deep MLP). Loads are clamped (always
// in-bounds); only stores are guarded for the tail.
// ---------------------------------------------------------------------------
__global__ __launch_bounds__(256) void gather_kernel(
    const int* __restrict__ src,
    const int* __restrict__ dst,
    float* __restrict__ out,
    int E, int N, int total_rows)
{
    const int t = threadIdx.x;
    const int i = t >> 4;             // row slot within block tile (0..15)
    const int c = t & 15;             // float4 chunk within row (D=64 -> 16 f4)
    const int base = blockIdx.x * 64 + i;

    const float4* __restrict__ hs4 = reinterpret_cast<const float4*>(g_hs);
    const float4* __restrict__ hd4 = reinterpret_cast<const float4*>(g_hd);

    // ---- index phase: all address math, no data-dependent branches ----
    int rowv[4];
    size_t aoff[4], doff[4];
#pragma unroll
    for (int r = 0; r < 4; ++r) {
        int row = base + r * 16;
        rowv[r] = row;
        int rc = row < total_rows ? row : (total_rows - 1);   // clamp, not branch
        int e = rc, b = 0;
#pragma unroll
        for (int q = 0; q < 3; ++q) {                          // B<=4, pure SELs
            int ge = (e >= E);
            e -= ge ? E : 0;
            b += ge;
        }
        int sn = __ldg(src + e);     // 16 lanes same addr -> broadcast
        int dn = __ldg(dst + e);
        aoff[r] = ((size_t)(b * N + sn) << 4) + c;
        doff[r] = ((size_t)(b * N + dn) << 4) + c;
    }

    // ---- gather phase: 8 independent LDG.128 back-to-back ----
    float4 a[4], d[4];
#pragma unroll
    for (int r = 0; r < 4; ++r) a[r] = __ldg(hs4 + aoff[r]);
#pragma unroll
    for (int r = 0; r < 4; ++r) d[r] = __ldg(hd4 + doff[r]);

    // ---- combine + streaming store (guarded) ----
#pragma unroll
    for (int r = 0; r < 4; ++r) {
        if (rowv[r] < total_rows) {
            float4 o;
            o.x = (a[r].x + d[r].x) * INV_SQRT_2;
            o.y = (a[r].y + d[r].y) * INV_SQRT_2;
            o.z = (a[r].z + d[r].z) * INV_SQRT_2;
            o.w = (a[r].w + d[r].w) * INV_SQRT_2;
            __stcs(reinterpret_cast<float4*>(out) + ((size_t)rowv[r] << 4) + c, o);
        }
    }
}

// ---------------------------------------------------------------------------
extern "C" void kernel_launch(void* const* d_in, const int* in_sizes, int n_in,
                              void* d_out, int out_size)
{
    const float* x    = (const float*)d_in[0];   // (B, N, 64)
    const int*   src  = (const int*)d_in[1];     // (E,) int32
    const int*   dst  = (const int*)d_in[2];     // (E,) int32
    const float* Wsrc = (const float*)d_in[3];   // (64, 64)
    const float* Wdst = (const float*)d_in[4];   // (64, 64)

    const int D = 64;
    const int E = in_sizes[1];
    const int M = in_sizes[0] / D;               // B*N
    const int total_rows = out_size / D;         // B*E (1.6M, fits int32)
    const int B = total_rows / E;
    const int N = M / B;

    const int SMEM_BYTES = 64 * 1024;   // Xd 32 KB + Ws 32 KB
    cudaFuncSetAttribute(transform_kernel,
                         cudaFuncAttributeMaxDynamicSharedMemorySize, SMEM_BYTES);

    // Phase 1: node transform (single launch; W loaded once per block)
    {
        int grid = (M + 63) / 64;
        transform_kernel<<<grid, 128, SMEM_BYTES>>>(x, Wsrc, Wdst, M);
    }
    // Phase 2: edge gather (64 rows per block)
    {
        int blocks = (total_rows + 63) / 64;
        gather_kernel<<<blocks, 256>>>(src, dst, (float*)d_out, E, N, total_rows);
    }
}